// round 17
// baseline (speedup 1.0000x reference)
#include <cuda_runtime.h>
#include <cuda_bf16.h>
#include <math.h>
#include <stdint.h>

#define T_STEPS 512
#define STATE   1024
#define EMBD    512
#define VOCAB   32000
#define G4      4096   // 4*STATE

// ---------------- scratch (no allocations allowed) ----------------
__device__ float g_embs[T_STEPS * EMBD];      // gathered embeddings [T,E]
__device__ float g_gbias[G4];                 // b_ih + b_hh + W_ih[:,E:]@fixed
__device__ float g_zf[VOCAB];                 // Z @ fixed
__device__ float g_gatesx[T_STEPS * G4];      // embs @ W_ihE^T + gbias
__device__ float g_hs[T_STEPS * STATE];       // h_t outputs
// tagged h publication: [parity][cta][4 x float4 {h_even, tag, h_odd, tag}]
__device__ float4 g_tagged[2 * 128 * 4];

// split-bf16 operands for the tensor-core GEMMs
__device__ __nv_bfloat16 g_X_hi[VOCAB * STATE];
__device__ __nv_bfloat16 g_X_lo[VOCAB * STATE];
__device__ __nv_bfloat16 g_Y_hi[VOCAB * EMBD];
__device__ __nv_bfloat16 g_Y_lo[VOCAB * EMBD];
__device__ __nv_bfloat16 g_hs_hi[T_STEPS * STATE];
__device__ __nv_bfloat16 g_hs_lo[T_STEPS * STATE];
__device__ __nv_bfloat16 g_e_hi[T_STEPS * EMBD];
__device__ __nv_bfloat16 g_e_lo[T_STEPS * EMBD];
__device__ __nv_bfloat16 g_Wx_hi[G4 * EMBD];   // W_ih[:, :EMBD] hi
__device__ __nv_bfloat16 g_Wx_lo[G4 * EMBD];   // W_ih[:, :EMBD] lo

// ======================= PTX helpers (base-target-safe) =======================
__device__ __forceinline__ uint32_t smem_u32(const void* p) {
    uint32_t a;
    asm("{ .reg .u64 t; cvta.to.shared.u64 t, %1; cvt.u32.u64 %0, t; }" : "=r"(a) : "l"(p));
    return a;
}
__device__ __forceinline__ void cp16(uint32_t dst, const void* src) {
    asm volatile("cp.async.cg.shared.global [%0], [%1], 16;" :: "r"(dst), "l"(src));
}
#define CP_COMMIT() asm volatile("cp.async.commit_group;" ::: "memory")
#define CP_WAIT1()  asm volatile("cp.async.wait_group 1;" ::: "memory")

#define LDSM4(r, addr)                                                         \
    asm volatile("ldmatrix.sync.aligned.m8n8.x4.shared.b16 {%0,%1,%2,%3}, [%4];" \
        : "=r"((r)[0]), "=r"((r)[1]), "=r"((r)[2]), "=r"((r)[3]) : "r"(addr))

#define MMA16816(d, a, b0, b1)                                                 \
    asm volatile("mma.sync.aligned.m16n8k16.row.col.f32.bf16.bf16.f32 "        \
        "{%0,%1,%2,%3}, {%4,%5,%6,%7}, {%8,%9}, {%0,%1,%2,%3};"                \
        : "+f"((d)[0]), "+f"((d)[1]), "+f"((d)[2]), "+f"((d)[3])               \
        : "r"((a)[0]), "r"((a)[1]), "r"((a)[2]), "r"((a)[3]), "r"(b0), "r"(b1))

__device__ __forceinline__ uint32_t sw128(uint32_t off) {
    return off ^ ((off >> 3) & 0x70);
}

// ---------------- prep: gather embeddings + reset tagged slots ----------------
__global__ void prep_kernel(const int* __restrict__ ids,
                            const float* __restrict__ emb_table) {
    int t = blockIdx.x;
    int src = ids[(t == 0) ? (T_STEPS - 1) : (t - 1)];
    const float4* e = (const float4*)(emb_table + (size_t)src * EMBD);
    float4* dst = (float4*)(g_embs + t * EMBD);
    dst[threadIdx.x] = e[threadIdx.x];
    if (blockIdx.x == 0) {
#pragma unroll
        for (int i = 0; i < 8; i++)
            g_tagged[threadIdx.x * 8 + i] = make_float4(0.f, 0.f, 0.f, 0.f);
    }
}

// ---------------- fp32 -> (hi, lo) bf16 split (contiguous) ----------------
__global__ void conv_split_kernel(const float* __restrict__ src,
                                  __nv_bfloat16* __restrict__ hi,
                                  __nv_bfloat16* __restrict__ lo, int n4) {
    int i = blockIdx.x * blockDim.x + threadIdx.x;
    if (i >= n4) return;
    float4 v = ((const float4*)src)[i];
    __nv_bfloat16 h0 = __float2bfloat16(v.x);
    __nv_bfloat16 h1 = __float2bfloat16(v.y);
    __nv_bfloat16 h2 = __float2bfloat16(v.z);
    __nv_bfloat16 h3 = __float2bfloat16(v.w);
    __nv_bfloat16 l0 = __float2bfloat16(v.x - __bfloat162float(h0));
    __nv_bfloat16 l1 = __float2bfloat16(v.y - __bfloat162float(h1));
    __nv_bfloat16 l2 = __float2bfloat16(v.z - __bfloat162float(h2));
    __nv_bfloat16 l3 = __float2bfloat16(v.w - __bfloat162float(h3));
    ((__nv_bfloat162*)hi)[2 * i]     = __nv_bfloat162(h0, h1);
    ((__nv_bfloat162*)hi)[2 * i + 1] = __nv_bfloat162(h2, h3);
    ((__nv_bfloat162*)lo)[2 * i]     = __nv_bfloat162(l0, l1);
    ((__nv_bfloat162*)lo)[2 * i + 1] = __nv_bfloat162(l2, l3);
}

// ---------------- fp32 -> (hi, lo) bf16 split (strided rows) ----------------
__global__ void conv_split_strided_kernel(const float* __restrict__ src,
                                          int src_ld4, int row4,
                                          __nv_bfloat16* __restrict__ hi,
                                          __nv_bfloat16* __restrict__ lo, int n4) {
    int i = blockIdx.x * blockDim.x + threadIdx.x;
    if (i >= n4) return;
    int row = i / row4, c = i - row * row4;
    float4 v = ((const float4*)src)[(size_t)row * src_ld4 + c];
    __nv_bfloat16 h0 = __float2bfloat16(v.x);
    __nv_bfloat16 h1 = __float2bfloat16(v.y);
    __nv_bfloat16 h2 = __float2bfloat16(v.z);
    __nv_bfloat16 h3 = __float2bfloat16(v.w);
    __nv_bfloat16 l0 = __float2bfloat16(v.x - __bfloat162float(h0));
    __nv_bfloat16 l1 = __float2bfloat16(v.y - __bfloat162float(h1));
    __nv_bfloat16 l2 = __float2bfloat16(v.z - __bfloat162float(h2));
    __nv_bfloat16 l3 = __float2bfloat16(v.w - __bfloat162float(h3));
    ((__nv_bfloat162*)hi)[2 * i]     = __nv_bfloat162(h0, h1);
    ((__nv_bfloat162*)hi)[2 * i + 1] = __nv_bfloat162(h2, h3);
    ((__nv_bfloat162*)lo)[2 * i]     = __nv_bfloat162(l0, l1);
    ((__nv_bfloat162*)lo)[2 * i + 1] = __nv_bfloat162(l2, l3);
}

// ---------------- row-dot vs fixed=[h0,c0]: one warp per row ----------------
__global__ void rowdot_kernel(const float* __restrict__ Mat, int ldm4,
                              const float* __restrict__ vA,
                              const float* __restrict__ vB,
                              const float* __restrict__ add0,
                              const float* __restrict__ add1,
                              float* __restrict__ out) {
    __shared__ float v[2048];
    for (int i = threadIdx.x; i < 2048; i += blockDim.x)
        v[i] = (i < 1024) ? vA[i] : vB[i - 1024];
    __syncthreads();
    int warp = threadIdx.x >> 5, lane = threadIdx.x & 31;
    int row = blockIdx.x * 8 + warp;
    const float4* m4 = (const float4*)Mat + (size_t)row * ldm4;
    const float4* v4 = (const float4*)v;
    float s = 0.f;
#pragma unroll
    for (int i = 0; i < 16; i++) {
        float4 a = m4[i * 32 + lane];
        float4 b = v4[i * 32 + lane];
        s += a.x * b.x + a.y * b.y + a.z * b.z + a.w * b.w;
    }
#pragma unroll
    for (int o = 16; o; o >>= 1) s += __shfl_xor_sync(0xffffffffu, s, o);
    if (lane == 0) {
        if (add0) s += add0[row];
        if (add1) s += add1[row];
        out[row] = s;
    }
}

// ---------------- persistent LSTM scan v8: warp-local consumption ------------
__global__ __launch_bounds__(512, 1)
void scan_kernel(const float* __restrict__ W_hh, const float* __restrict__ h0,
                 const float* __restrict__ c0) {
    __shared__ float4 h4s[256];
    __shared__ float psum[2][32 * 17];
    float* hf = (float*)h4s;

    const int tid = threadIdx.x;
    const int bid = blockIdx.x;
    const int base_j = bid * 8;
    const int r = tid & 31;
    const int seg = tid >> 5;
    const int gr = ((r >> 3) << 10) + base_j + (r & 7);

    ulonglong2 wreg[16];
    {
        const ulonglong2* src =
            (const ulonglong2*)W_hh + (size_t)gr * 256 + seg * 16;
#pragma unroll
        for (int i = 0; i < 16; i++) wreg[i] = src[i];
    }
    float c_reg = (tid < 8) ? c0[base_j + tid] : 0.f;
    __syncthreads();

#pragma unroll 1
    for (int t = 0; t < T_STEPS; t++) {
        float gx = 0.f;
        if (tid < 32)
            gx = g_gatesx[(size_t)t * G4 + ((tid >> 3) << 10) + base_j + (tid & 7)];

        if (t == 0) {
            float2 v = ((const float2*)h0)[tid];
            hf[2 * tid] = v.x;
            hf[2 * tid + 1] = v.y;
        } else {
            const unsigned int want = (unsigned int)t;
            const float4* p0 = g_tagged + (((t - 1) & 1) << 9) + tid;
            float4 a0 = make_float4(0, 0, 0, 0);
            int d0 = 0;
            do {
                asm volatile("ld.volatile.global.v4.f32 {%0,%1,%2,%3}, [%4];"
                             : "=f"(a0.x), "=f"(a0.y), "=f"(a0.z), "=f"(a0.w)
                             : "l"(p0));
                d0 = (__float_as_uint(a0.y) >= want) &&
                     (__float_as_uint(a0.w) >= want);
            } while (!d0);
            hf[2 * tid] = a0.x;
            hf[2 * tid + 1] = a0.z;
        }
        __syncwarp();

        const ulonglong2* hseg = (const ulonglong2*)&h4s[seg * 16];
        unsigned long long acc0 = 0ull, acc1 = 0ull;
#pragma unroll
        for (int i = 0; i < 16; i++) {
            ulonglong2 b = hseg[i];
            ulonglong2 w = wreg[i];
            asm("fma.rn.f32x2 %0, %1, %2, %0;" : "+l"(acc0) : "l"(w.x), "l"(b.x));
            asm("fma.rn.f32x2 %0, %1, %2, %0;" : "+l"(acc1) : "l"(w.y), "l"(b.y));
        }
        float a0, a1, a2, a3;
        asm("mov.b64 {%0,%1}, %2;" : "=f"(a0), "=f"(a1) : "l"(acc0));
        asm("mov.b64 {%0,%1}, %2;" : "=f"(a2), "=f"(a3) : "l"(acc1));
        psum[t & 1][r * 17 + seg] = (a0 + a1) + (a2 + a3);
        __syncthreads();

        if (tid < 32) {
            float s = gx;
            const float* pr = &psum[t & 1][tid * 17];
#pragma unroll
            for (int q = 0; q < 16; q++) s += pr[q];
            int g2 = tid >> 3;
            float scale = (g2 == 2) ? 2.f * s : s;
            float sig = 1.f / (1.f + __expf(-scale));
            float act = (g2 == 2) ? (2.f * sig - 1.f) : sig;
            int j = tid & 7;
            float iv = __shfl_sync(0xffffffffu, act, j);
            float fv = __shfl_sync(0xffffffffu, act, j + 8);
            float gv = __shfl_sync(0xffffffffu, act, j + 16);
            float ov = __shfl_sync(0xffffffffu, act, j + 24);
            float hval = 0.f;
            if (tid < 8) {
                c_reg = fv * c_reg + iv * gv;
                float tc = 2.f / (1.f + __expf(-2.f * c_reg)) - 1.f;
                hval = ov * tc;
                g_hs[(size_t)t * STATE + base_j + tid] = hval;
            }
            float h_e = __shfl_sync(0xffffffffu, hval, tid * 2);
            float h_o = __shfl_sync(0xffffffffu, hval, tid * 2 + 1);
            if (tid < 4) {
                float tagf = __uint_as_float((unsigned int)(t + 1));
                float4* dst = g_tagged + ((t & 1) << 9) + bid * 4 + tid;
                asm volatile("st.volatile.global.v4.f32 [%0], {%1,%2,%3,%4};"
                             :: "l"(dst), "f"(h_e), "f"(tagf), "f"(h_o), "f"(tagf)
                             : "memory");
            }
        }
    }
}

// ============== mma.sync split-bf16 GEMM machinery ==============
#define TILE_B   16384u
#define STAGE_B  (4u * TILE_B)       // gates kernel stage (A hi/lo + B hi/lo)
#define GATES_SMEM (2 * STAGE_B)
#define STAGE_B2 (6u * TILE_B)       // scores stage (A0,A1 hi/lo + B hi/lo)
#define SCORES_SMEM (2 * STAGE_B2)   // 192 KB
#define NCHUNK 24

// 128-row loader (gates kernel)
__device__ __forceinline__ void load_stage(const __nv_bfloat16* Ah,
                                           const __nv_bfloat16* Al,
                                           const __nv_bfloat16* Bh,
                                           const __nv_bfloat16* Bl,
                                           int ld, int m0, int n0, int k0,
                                           uint32_t stage, int tid) {
#pragma unroll
    for (int i = 0; i < 16; i++) {
        int id = tid + (i << 8);
        int tile = id >> 10;
        int within = id & 1023;
        int row = within >> 3;
        int c = within & 7;
        const __nv_bfloat16* bp = (tile == 0) ? Ah : (tile == 1) ? Al
                                 : (tile == 2) ? Bh : Bl;
        int grow = ((tile < 2) ? m0 : n0) + row;
        const __nv_bfloat16* src = bp + (size_t)grow * ld + k0 + (c << 3);
        uint32_t dst = stage + ((uint32_t)tile << 14)
                     + sw128(((uint32_t)row << 7) + ((uint32_t)c << 4));
        cp16(dst, src);
    }
}

// 256-row loader (scores kernel): tiles 0:A0hi 1:A0lo 2:A1hi 3:A1lo 4:Bhi 5:Blo
__device__ __forceinline__ void load_stage2(const __nv_bfloat16* Ah,
                                            const __nv_bfloat16* Al,
                                            const __nv_bfloat16* Bh,
                                            const __nv_bfloat16* Bl,
                                            int ld, int m0, int n0, int k0,
                                            uint32_t stage, int tid) {
#pragma unroll
    for (int i = 0; i < 24; i++) {
        int id = tid + (i << 8);          // 0..6143
        int tile = id >> 10;              // 0..5
        int within = id & 1023;
        int row = within >> 3;
        int c = within & 7;
        const __nv_bfloat16* bp;
        int grow;
        if (tile < 4) {
            bp = (tile & 1) ? Al : Ah;
            grow = m0 + ((tile >> 1) << 7) + row;
        } else {
            bp = (tile == 4) ? Bh : Bl;
            grow = n0 + row;
        }
        const __nv_bfloat16* src = bp + (size_t)grow * ld + k0 + (c << 3);
        uint32_t dst = stage + ((uint32_t)tile << 14)
                     + sw128(((uint32_t)row << 7) + ((uint32_t)c << 4));
        cp16(dst, src);
    }
}

// 128-row chunk (gates kernel)
__device__ __forceinline__ void mma_chunk(uint32_t stg, int wm, int wn, int lane,
                                          float acc[2][8][4]) {
#pragma unroll
    for (int ks = 0; ks < 4; ks++) {
        uint32_t kbyte = ((uint32_t)ks << 5) + (((uint32_t)lane >> 4) << 4);
        uint32_t bh[4][4], bl[4][4];
#pragma unroll
        for (int q = 0; q < 4; q++) {
            uint32_t roff = ((uint32_t)(wn + q * 16 + (lane & 15))) << 7;
            LDSM4(bh[q], stg + (2u << 14) + sw128(roff + kbyte));
            LDSM4(bl[q], stg + (3u << 14) + sw128(roff + kbyte));
        }
#pragma unroll
        for (int mt = 0; mt < 2; mt++) {
            uint32_t roff = ((uint32_t)(wm + mt * 16 + (lane & 15))) << 7;
            uint32_t a_h[4], a_l[4];
            LDSM4(a_h, stg + sw128(roff + kbyte));
            LDSM4(a_l, stg + (1u << 14) + sw128(roff + kbyte));
#pragma unroll
            for (int q = 0; q < 4; q++) {
#pragma unroll
                for (int h = 0; h < 2; h++) {
                    int nt = q * 2 + h;
                    MMA16816(acc[mt][nt], a_h, bh[q][h], bh[q][h + 2]);
                    MMA16816(acc[mt][nt], a_h, bl[q][h], bl[q][h + 2]);
                    MMA16816(acc[mt][nt], a_l, bh[q][h], bh[q][h + 2]);
                }
            }
        }
    }
}

// 256-row chunk (scores kernel)
__device__ __forceinline__ void mma_chunk2(uint32_t stg, int wm, int wn, int lane,
                                           float acc[4][8][4]) {
#pragma unroll
    for (int ks = 0; ks < 4; ks++) {
        uint32_t kbyte = ((uint32_t)ks << 5) + (((uint32_t)lane >> 4) << 4);
        uint32_t bh[4][4], bl[4][4];
#pragma unroll
        for (int q = 0; q < 4; q++) {
            uint32_t roff = ((uint32_t)(wn + q * 16 + (lane & 15))) << 7;
            LDSM4(bh[q], stg + (4u << 14) + sw128(roff + kbyte));
            LDSM4(bl[q], stg + (5u << 14) + sw128(roff + kbyte));
        }
#pragma unroll
        for (int mt = 0; mt < 4; mt++) {
            uint32_t abase = stg + ((uint32_t)((mt >> 1) << 1) << 14);
            uint32_t roff = ((uint32_t)(wm + (mt & 1) * 16 + (lane & 15))) << 7;
            uint32_t a_h[4], a_l[4];
            LDSM4(a_h, abase + sw128(roff + kbyte));
            LDSM4(a_l, abase + (1u << 14) + sw128(roff + kbyte));
#pragma unroll
            for (int q = 0; q < 4; q++) {
#pragma unroll
                for (int h = 0; h < 2; h++) {
                    int nt = q * 2 + h;
                    MMA16816(acc[mt][nt], a_h, bh[q][h], bh[q][h + 2]);
                    MMA16816(acc[mt][nt], a_h, bl[q][h], bl[q][h + 2]);
                    MMA16816(acc[mt][nt], a_l, bh[q][h], bh[q][h + 2]);
                }
            }
        }
    }
}

__device__ __forceinline__ void mma_epilogue(float acc[2][8][4], int wm, int wn,
                                             int lane, int m0, int n0,
                                             const float* bias, float* out, int ldc) {
#pragma unroll
    for (int mt = 0; mt < 2; mt++) {
        int mrow = m0 + wm + mt * 16 + (lane >> 2);
#pragma unroll
        for (int half = 0; half < 2; half++) {
            float* orow = out + (size_t)(mrow + half * 8) * ldc;
#pragma unroll
            for (int nt = 0; nt < 8; nt++) {
                int n = n0 + wn + nt * 8 + (lane & 3) * 2;
                float2 z = *(const float2*)&bias[n];
                float2 r;
                r.x = acc[mt][nt][half * 2 + 0] + z.x;
                r.y = acc[mt][nt][half * 2 + 1] + z.y;
                *(float2*)&orow[n] = r;
            }
        }
    }
}

// scores = hs@X^T (16 chunks) + embs@Y^T (8 chunks) + zf; 256x128 per CTA
__global__ __launch_bounds__(256, 1)
void scores_mma_kernel(const __nv_bfloat16* __restrict__ Ah,
                       const __nv_bfloat16* __restrict__ Al,
                       const __nv_bfloat16* __restrict__ Xh,
                       const __nv_bfloat16* __restrict__ Xl,
                       const __nv_bfloat16* __restrict__ Eh,
                       const __nv_bfloat16* __restrict__ El,
                       const __nv_bfloat16* __restrict__ Yh,
                       const __nv_bfloat16* __restrict__ Yl,
                       const float* __restrict__ zf,
                       float* __restrict__ out) {
    extern __shared__ __align__(16) char dsm[];
    uint32_t base = smem_u32(dsm);
    const int tid = threadIdx.x, wid = tid >> 5, lane = tid & 31;
    const int m0 = blockIdx.x * 256, n0 = blockIdx.y * 128;
    const int wm = (wid & 3) * 32;
    const int wn = (wid >> 2) * 64;

    float acc[4][8][4];
#pragma unroll
    for (int a = 0; a < 4; a++)
#pragma unroll
        for (int b = 0; b < 8; b++)
#pragma unroll
            for (int c = 0; c < 4; c++) acc[a][b][c] = 0.f;

    load_stage2(Ah, Al, Xh, Xl, STATE, m0, n0, 0, base, tid);
    CP_COMMIT();
    load_stage2(Ah, Al, Xh, Xl, STATE, m0, n0, 64, base + STAGE_B2, tid);
    CP_COMMIT();

#pragma unroll 1
    for (int s = 0; s < NCHUNK; s++) {
        uint32_t stg = base + (uint32_t)(s & 1) * STAGE_B2;
        CP_WAIT1();
        __syncthreads();
        mma_chunk2(stg, wm, wn, lane, acc);
        __syncthreads();
        if (s + 2 < NCHUNK) {
            int s2 = s + 2;
            if (s2 < 16)
                load_stage2(Ah, Al, Xh, Xl, STATE, m0, n0, s2 * 64, stg, tid);
            else
                load_stage2(Eh, El, Yh, Yl, EMBD, m0, n0, (s2 - 16) * 64, stg, tid);
            CP_COMMIT();
        }
    }

    // epilogue for both 128-row blocks
#pragma unroll
    for (int mt = 0; mt < 4; mt++) {
        int mrow = m0 + ((mt >> 1) << 7) + wm + (mt & 1) * 16 + (lane >> 2);
#pragma unroll
        for (int half = 0; half < 2; half++) {
            float* orow = out + (size_t)(mrow + half * 8) * VOCAB;
#pragma unroll
            for (int nt = 0; nt < 8; nt++) {
                int n = n0 + wn + nt * 8 + (lane & 3) * 2;
                float2 z = *(const float2*)&zf[n];
                float2 r;
                r.x = acc[mt][nt][half * 2 + 0] + z.x;
                r.y = acc[mt][nt][half * 2 + 1] + z.y;
                *(float2*)&orow[n] = r;
            }
        }
    }
}

// gates_x = embs @ W_ihE^T + gbias  (M=512, N=4096, K=512: 8 chunks)
__global__ __launch_bounds__(256, 1)
void gates_mma_kernel(const __nv_bfloat16* __restrict__ Ah,
                      const __nv_bfloat16* __restrict__ Al,
                      const __nv_bfloat16* __restrict__ Bh,
                      const __nv_bfloat16* __restrict__ Bl,
                      const float* __restrict__ bias,
                      float* __restrict__ out) {
    extern __shared__ __align__(16) char dsm[];
    uint32_t base = smem_u32(dsm);
    const int tid = threadIdx.x, wid = tid >> 5, lane = tid & 31;
    const int m0 = blockIdx.x * 128, n0 = blockIdx.y * 128;
    const int wm = (wid & 3) * 32;
    const int wn = (wid >> 2) * 64;

    float acc[2][8][4];
#pragma unroll
    for (int a = 0; a < 2; a++)
#pragma unroll
        for (int b = 0; b < 8; b++)
#pragma unroll
            for (int c = 0; c < 4; c++) acc[a][b][c] = 0.f;

    load_stage(Ah, Al, Bh, Bl, EMBD, m0, n0, 0, base, tid);
    CP_COMMIT();
    load_stage(Ah, Al, Bh, Bl, EMBD, m0, n0, 64, base + STAGE_B, tid);
    CP_COMMIT();

#pragma unroll 1
    for (int s = 0; s < 8; s++) {
        uint32_t stg = base + (uint32_t)(s & 1) * STAGE_B;
        CP_WAIT1();
        __syncthreads();
        mma_chunk(stg, wm, wn, lane, acc);
        __syncthreads();
        if (s + 2 < 8) {
            load_stage(Ah, Al, Bh, Bl, EMBD, m0, n0, (s + 2) * 64, stg, tid);
            CP_COMMIT();
        }
    }
    mma_epilogue(acc, wm, wn, lane, m0, n0, bias, out, G4);
}

// ---------------- launch ----------------
extern "C" void kernel_launch(void* const* d_in, const int* in_sizes, int n_in,
                              void* d_out, int out_size) {
    (void)in_sizes; (void)n_in; (void)out_size;
    const float* h0   = (const float*)d_in[0];
    const float* c0   = (const float*)d_in[1];
    const int*   ids  = (const int*)d_in[2];
    const float* embT = (const float*)d_in[3];
    const float* W_ih = (const float*)d_in[4];
    const float* W_hh = (const float*)d_in[5];
    const float* b_ih = (const float*)d_in[6];
    const float* b_hh = (const float*)d_in[7];
    const float* X    = (const float*)d_in[8];
    const float* Y    = (const float*)d_in[9];
    const float* Z    = (const float*)d_in[10];
    float* out = (float*)d_out;

    float *p_embs, *p_gbias, *p_zf, *p_gatesx, *p_hs;
    cudaGetSymbolAddress((void**)&p_embs, g_embs);
    cudaGetSymbolAddress((void**)&p_gbias, g_gbias);
    cudaGetSymbolAddress((void**)&p_zf, g_zf);
    cudaGetSymbolAddress((void**)&p_gatesx, g_gatesx);
    cudaGetSymbolAddress((void**)&p_hs, g_hs);
    __nv_bfloat16 *pXh, *pXl, *pYh, *pYl, *pHh, *pHl, *pEh, *pEl, *pWh, *pWl;
    cudaGetSymbolAddress((void**)&pXh, g_X_hi);
    cudaGetSymbolAddress((void**)&pXl, g_X_lo);
    cudaGetSymbolAddress((void**)&pYh, g_Y_hi);
    cudaGetSymbolAddress((void**)&pYl, g_Y_lo);
    cudaGetSymbolAddress((void**)&pHh, g_hs_hi);
    cudaGetSymbolAddress((void**)&pHl, g_hs_lo);
    cudaGetSymbolAddress((void**)&pEh, g_e_hi);
    cudaGetSymbolAddress((void**)&pEl, g_e_lo);
    cudaGetSymbolAddress((void**)&pWh, g_Wx_hi);
    cudaGetSymbolAddress((void**)&pWl, g_Wx_lo);

    // 1) gather embeddings, reset tagged slots
    prep_kernel<<<T_STEPS, 128>>>(ids, embT);

    // 2) gbias = b_ih + b_hh + W_ih[:,E:] @ fixed
    rowdot_kernel<<<G4 / 8, 256>>>(W_ih + EMBD, (EMBD + 2 * STATE) / 4,
                                   h0, c0, b_ih, b_hh, p_gbias);

    // 3) zf = Z @ fixed
    rowdot_kernel<<<VOCAB / 8, 256>>>(Z, (2 * STATE) / 4,
                                      h0, c0, nullptr, nullptr, p_zf);

    // 4) split conversions: X, Y, embs, W_ihE (strided)
    conv_split_kernel<<<(VOCAB * STATE / 4 + 255) / 256, 256>>>(X, pXh, pXl,
                                                                VOCAB * STATE / 4);
    conv_split_kernel<<<(VOCAB * EMBD / 4 + 255) / 256, 256>>>(Y, pYh, pYl,
                                                               VOCAB * EMBD / 4);
    conv_split_kernel<<<(T_STEPS * EMBD / 4 + 255) / 256, 256>>>(p_embs, pEh, pEl,
                                                                 T_STEPS * EMBD / 4);
    conv_split_strided_kernel<<<(G4 * EMBD / 4 + 255) / 256, 256>>>(
        W_ih, (EMBD + 2 * STATE) / 4, EMBD / 4, pWh, pWl, G4 * EMBD / 4);

    // 5) gates_x = embs @ W_ihE^T + gbias via split-bf16 mma
    {
        cudaFuncSetAttribute(gates_mma_kernel,
                             cudaFuncAttributeMaxDynamicSharedMemorySize, GATES_SMEM);
        dim3 grid(T_STEPS / 128, G4 / 128);
        gates_mma_kernel<<<grid, 256, GATES_SMEM>>>(pEh, pEl, pWh, pWl,
                                                    p_gbias, p_gatesx);
    }

    // 6) sequential LSTM scan (v8: warp-local consumption)
    scan_kernel<<<128, 512>>>(W_hh, h0, c0);

    // 7) hs -> hi/lo bf16
    conv_split_kernel<<<(T_STEPS * STATE / 4 + 255) / 256, 256>>>(p_hs, pHh, pHl,
                                                                  T_STEPS * STATE / 4);

    // 8) scores via split-bf16 mma, 256-row CTAs (B tiles shared)
    {
        cudaFuncSetAttribute(scores_mma_kernel,
                             cudaFuncAttributeMaxDynamicSharedMemorySize, SCORES_SMEM);
        dim3 grid(T_STEPS / 256, VOCAB / 128);
        scores_mma_kernel<<<grid, 256, SCORES_SMEM>>>(pHh, pHl, pXh, pXl,
                                                      pEh, pEl, pYh, pYl,
                                                      p_zf, out);
    }
}